// round 2
// baseline (speedup 1.0000x reference)
#include <cuda_runtime.h>
#include <cstdint>
#include <cstddef>

#define BATCH 8
#define P 2048
#define D 64
#define FEPS 0.1f
// log2(e)/eps
#define INV 14.426950408889634f
// eps*ln(2)
#define EPSLN2 0.06931471805599453f
#define NMAT ((size_t)BATCH * P * P)

// ---------------- scratch (static device globals; no runtime allocation) ----
__device__ float g_u[BATCH * P];
__device__ float g_v[BATCH * P];
__device__ float g_xn[BATCH * P];
__device__ float g_yn[BATCH * P];
__device__ float g_vpm[BATCH * 8 * P];   // v-update partial max   [b][chunk][j]
__device__ float g_vps[BATCH * 8 * P];   // v-update partial sum   [b][chunk][j]
__device__ float g_errp[2048];           // per-U-block |du| partials
__device__ float g_costp[BATCH * P];     // per-row pi*C partials
__device__ int   g_done[2];              // parity double-buffered freeze flag

__device__ __forceinline__ float eps_log_marginal() {
    // EPS * log(1/P + 1e-8), computed with f32 semantics like the reference
    return FEPS * logf(1.0f / 2048.0f + 1e-8f);
}

// ---------------- init --------------------------------------------------------
__global__ void k_init() {
    int i = blockIdx.x * blockDim.x + threadIdx.x;
    if (i < BATCH * P) { g_u[i] = 0.0f; g_v[i] = 0.0f; }
    if (i == 0) { g_done[0] = 0; g_done[1] = 0; }
}

// ---------------- squared norms (warp per point) ------------------------------
__global__ void k_norm(const float* __restrict__ x, const float* __restrict__ y) {
    int gw   = (blockIdx.x * blockDim.x + threadIdx.x) >> 5;
    int lane = threadIdx.x & 31;
    if (gw >= 2 * BATCH * P) return;
    bool isx = gw < BATCH * P;
    int p = isx ? gw : gw - BATCH * P;
    const float* src = isx ? x : y;
    float a0 = src[(size_t)p * D + lane];
    float a1 = src[(size_t)p * D + 32 + lane];
    float s = a0 * a0 + a1 * a1;
    #pragma unroll
    for (int o = 16; o; o >>= 1) s += __shfl_xor_sync(0xffffffffu, s, o);
    if (lane == 0) (isx ? g_xn : g_yn)[p] = s;
}

// ---------------- C = ||x||^2 + ||y||^2 - 2 x.y  (64x64 tile, fp32) -----------
__global__ void k_costmat(const float* __restrict__ x, const float* __restrict__ y,
                          float* __restrict__ Cout) {
    __shared__ float xs[64][65];   // [k][i]
    __shared__ float ys[64][65];   // [k][j]
    int b  = blockIdx.z;
    int i0 = blockIdx.y * 64;
    int j0 = blockIdx.x * 64;
    int tid = threadIdx.x;

    const float* xb = x + ((size_t)b * P + i0) * D;
    const float* yb = y + ((size_t)b * P + j0) * D;
    #pragma unroll
    for (int idx = tid; idx < 4096; idx += 256) {
        int p = idx >> 6, d = idx & 63;
        xs[d][p] = xb[(size_t)p * D + d];
        ys[d][p] = yb[(size_t)p * D + d];
    }
    __syncthreads();

    int tx = tid & 15, ty = tid >> 4;
    float acc[4][4];
    #pragma unroll
    for (int r = 0; r < 4; r++)
        #pragma unroll
        for (int c = 0; c < 4; c++) acc[r][c] = 0.0f;

    #pragma unroll 8
    for (int k = 0; k < 64; k++) {
        float rx[4], ry[4];
        #pragma unroll
        for (int r = 0; r < 4; r++) rx[r] = xs[k][ty * 4 + r];
        #pragma unroll
        for (int c = 0; c < 4; c++) ry[c] = ys[k][tx * 4 + c];
        #pragma unroll
        for (int r = 0; r < 4; r++)
            #pragma unroll
            for (int c = 0; c < 4; c++) acc[r][c] = fmaf(rx[r], ry[c], acc[r][c]);
    }

    float xnr[4], ynr[4];
    #pragma unroll
    for (int r = 0; r < 4; r++) xnr[r] = g_xn[b * P + i0 + ty * 4 + r];
    #pragma unroll
    for (int c = 0; c < 4; c++) ynr[c] = g_yn[b * P + j0 + tx * 4 + c];

    #pragma unroll
    for (int r = 0; r < 4; r++) {
        int row = i0 + ty * 4 + r;
        float4 v4;
        v4.x = xnr[r] + ynr[0] - 2.0f * acc[r][0];
        v4.y = xnr[r] + ynr[1] - 2.0f * acc[r][1];
        v4.z = xnr[r] + ynr[2] - 2.0f * acc[r][2];
        v4.w = xnr[r] + ynr[3] - 2.0f * acc[r][3];
        *reinterpret_cast<float4*>(Cout + ((size_t)b * P + row) * P + j0 + tx * 4) = v4;
    }
}

// ---------------- u update: warp per row, two-pass LSE ------------------------
__global__ void k_u(const float* __restrict__ Cm, int par) {
    if (g_done[par]) { if (blockIdx.x == 0 && threadIdx.x == 0) {} return; }
    __shared__ float vw[P];
    __shared__ float serr[8];
    int tid = threadIdx.x;
    int rbase = blockIdx.x * 8;
    int b = rbase >> 11;
    const float* vrow = g_v + b * P;
    for (int j = tid; j < P; j += 256) vw[j] = vrow[j] * INV;
    __syncthreads();

    int warp = tid >> 5, lane = tid & 31;
    int r = rbase + warp;
    const float* Crow = Cm + (size_t)r * P;

    float m = -3.4e38f;
    #pragma unroll 8
    for (int j = lane; j < P; j += 32)
        m = fmaxf(m, fmaf(Crow[j], -INV, vw[j]));
    #pragma unroll
    for (int o = 16; o; o >>= 1) m = fmaxf(m, __shfl_xor_sync(0xffffffffu, m, o));

    float s = 0.0f;
    #pragma unroll 8
    for (int j = lane; j < P; j += 32) {
        float d = fmaf(Crow[j], -INV, vw[j]) - m;
        if (d > -30.0f) s += exp2f(d);
    }
    #pragma unroll
    for (int o = 16; o; o >>= 1) s += __shfl_xor_sync(0xffffffffu, s, o);

    if (lane == 0) {
        float unew = eps_log_marginal() - EPSLN2 * (m + __log2f(s));
        float uold = g_u[r];
        g_u[r] = unew;
        serr[warp] = fabsf(unew - uold);
    }
    __syncthreads();
    if (tid == 0) {
        float e = 0.0f;
        #pragma unroll
        for (int i2 = 0; i2 < 8; i2++) e += serr[i2];
        g_errp[blockIdx.x] = e;
    }
}

// ---------------- v update stage 1: column partial LSE ------------------------
__global__ void k_v1(const float* __restrict__ Cm, int par) {
    if (g_done[par]) return;
    __shared__ float uw[256];
    int bx = blockIdx.x;
    int jt = bx & 15;
    int sc = (bx >> 4) & 7;
    int b  = bx >> 7;
    int i0 = sc * 256;
    int tid = threadIdx.x;   // 128
    uw[tid]       = g_u[b * P + i0 + tid] * INV;
    uw[tid + 128] = g_u[b * P + i0 + tid + 128] * INV;
    __syncthreads();

    int j = jt * 128 + tid;
    const float* Ccol = Cm + ((size_t)(b * P + i0)) * P + j;

    float m = -3.4e38f;
    #pragma unroll 8
    for (int i = 0; i < 256; i++)
        m = fmaxf(m, fmaf(Ccol[(size_t)i * P], -INV, uw[i]));

    float s = 0.0f;
    #pragma unroll 8
    for (int i = 0; i < 256; i++) {
        float d = fmaf(Ccol[(size_t)i * P], -INV, uw[i]) - m;
        if (d > -30.0f) s += exp2f(d);
    }
    int o = (b * 8 + sc) * P + j;
    g_vpm[o] = m;
    g_vps[o] = s;
}

// ---------------- v update stage 2: combine partials + convergence check ------
__global__ void k_v2(int par) {
    if (g_done[par]) {
        if (blockIdx.x == 0 && threadIdx.x == 0) g_done[par ^ 1] = 1;
        return;
    }
    int idx = blockIdx.x * 256 + threadIdx.x;   // == b*P + j
    int b = idx >> 11;
    int j = idx & (P - 1);

    float m = -3.4e38f;
    #pragma unroll
    for (int sc = 0; sc < 8; sc++) m = fmaxf(m, g_vpm[(b * 8 + sc) * P + j]);
    float sum = 0.0f;
    #pragma unroll
    for (int sc = 0; sc < 8; sc++)
        sum += g_vps[(b * 8 + sc) * P + j] * exp2f(g_vpm[(b * 8 + sc) * P + j] - m);

    g_v[idx] = eps_log_marginal() - EPSLN2 * (m + __log2f(sum));

    if (blockIdx.x == 0) {
        __shared__ float se[256];
        float e = 0.0f;
        for (int t = threadIdx.x; t < 2048; t += 256) e += g_errp[t];
        se[threadIdx.x] = e;
        __syncthreads();
        for (int o = 128; o; o >>= 1) {
            if (threadIdx.x < o) se[threadIdx.x] += se[threadIdx.x + o];
            __syncthreads();
        }
        if (threadIdx.x == 0)
            g_done[par ^ 1] = (se[0] * (1.0f / BATCH) < 0.1f) ? 1 : 0;
    }
}

// ---------------- pi = exp((u+v-C)/eps), partial cost -------------------------
__global__ void k_pi(const float* __restrict__ Cm, float* __restrict__ piOut) {
    __shared__ float vv[P];
    __shared__ float sacc[256];
    int r = blockIdx.x;
    int b = r >> 11;
    int tid = threadIdx.x;
    for (int j = tid; j < P; j += 256) vv[j] = g_v[b * P + j];
    float ur = g_u[r];
    __syncthreads();

    const float* Crow = Cm + (size_t)r * P;
    float* prow = piOut + (size_t)r * P;
    float acc = 0.0f;
    #pragma unroll 4
    for (int j = tid; j < P; j += 256) {
        float c = Crow[j];
        float a = (ur + vv[j] - c) * INV;
        float pv = (a > -126.0f) ? exp2f(a) : 0.0f;
        prow[j] = pv;
        acc = fmaf(pv, c, acc);
    }
    sacc[tid] = acc;
    __syncthreads();
    for (int o = 128; o; o >>= 1) {
        if (tid < o) sacc[tid] += sacc[tid + o];
        __syncthreads();
    }
    if (tid == 0) g_costp[r] = sacc[0];
}

__global__ void k_costred(float* __restrict__ costOut) {
    __shared__ float sb[256];
    int b = blockIdx.x;
    float e = 0.0f;
    for (int t = threadIdx.x; t < P; t += 256) e += g_costp[b * P + t];
    sb[threadIdx.x] = e;
    __syncthreads();
    for (int o = 128; o; o >>= 1) {
        if (threadIdx.x < o) sb[threadIdx.x] += sb[threadIdx.x + o];
        __syncthreads();
    }
    if (threadIdx.x == 0) costOut[b] = sb[0];
}

// ---------------- launch ------------------------------------------------------
extern "C" void kernel_launch(void* const* d_in, const int* in_sizes, int n_in,
                              void* d_out, int out_size) {
    (void)in_sizes; (void)n_in; (void)out_size;
    const float* x = (const float*)d_in[0];
    const float* y = (const float*)d_in[1];
    float* out  = (float*)d_out;
    float* cost = out;                      // [8]
    float* pi   = out + 8;                  // [8,2048,2048]
    float* Cm   = out + 8 + NMAT;           // [8,2048,2048]

    k_init<<<64, 256>>>();
    k_norm<<<4096, 256>>>(x, y);
    dim3 cg(32, 32, 8);
    k_costmat<<<cg, 256>>>(x, y, Cm);

    for (int k = 0; k < 100; k++) {
        int par = k & 1;
        k_u<<<2048, 256>>>(Cm, par);
        k_v1<<<1024, 128>>>(Cm, par);
        k_v2<<<64, 256>>>(par);
    }

    k_pi<<<16384, 256>>>(Cm, pi);
    k_costred<<<8, 256>>>(cost);
}

// round 4
// speedup vs baseline: 1.1925x; 1.1925x over previous
#include <cuda_runtime.h>
#include <cstdint>
#include <cstddef>

#define BATCH 8
#define P 2048
#define D 64
#define FEPS 0.1f
// log2(e)/eps
#define INV 14.426950408889634f
// eps*ln(2)
#define EPSLN2 0.06931471805599453f
#define NMAT ((size_t)BATCH * P * P)

// ---------------- scratch (static device globals; no runtime allocation) ----
__device__ __align__(16) float g_u[BATCH * P];
__device__ __align__(16) float g_v[BATCH * P];
__device__ float g_xn[BATCH * P];
__device__ float g_yn[BATCH * P];
__device__ float g_errp[2048];           // per-U-block |du| partials
__device__ float g_costp[BATCH * P];     // per-row pi*C partials
__device__ int   g_done[2];              // parity double-buffered freeze flag
__device__ __align__(16) float4 g_ct4[NMAT / 4];  // C transposed (134MB scratch)

__device__ __forceinline__ float ex2f(float x) {
    float r; asm("ex2.approx.f32 %0, %1;" : "=f"(r) : "f"(x)); return r;
}
__device__ __forceinline__ float lg2f_(float x) {
    float r; asm("lg2.approx.f32 %0, %1;" : "=f"(r) : "f"(x)); return r;
}
__device__ __forceinline__ float eps_log_marginal() {
    return FEPS * logf(1.0f / 2048.0f + 1e-8f);
}

// ---------------- init --------------------------------------------------------
__global__ void k_init() {
    int i = blockIdx.x * blockDim.x + threadIdx.x;
    if (i < BATCH * P) { g_u[i] = 0.0f; g_v[i] = 0.0f; }
    if (i == 0) { g_done[0] = 0; g_done[1] = 0; }
}

// ---------------- squared norms (warp per point) ------------------------------
__global__ void k_norm(const float* __restrict__ x, const float* __restrict__ y) {
    int gw   = (blockIdx.x * blockDim.x + threadIdx.x) >> 5;
    int lane = threadIdx.x & 31;
    if (gw >= 2 * BATCH * P) return;
    bool isx = gw < BATCH * P;
    int p = isx ? gw : gw - BATCH * P;
    const float* src = isx ? x : y;
    float a0 = src[(size_t)p * D + lane];
    float a1 = src[(size_t)p * D + 32 + lane];
    float s = a0 * a0 + a1 * a1;
    #pragma unroll
    for (int o = 16; o; o >>= 1) s += __shfl_xor_sync(0xffffffffu, s, o);
    if (lane == 0) (isx ? g_xn : g_yn)[p] = s;
}

// ---------------- C = ||x||^2 + ||y||^2 - 2 x.y  (+ transposed copy) ----------
__global__ void k_costmat(const float* __restrict__ x, const float* __restrict__ y,
                          float* __restrict__ Cout) {
    __shared__ float xs[64][65];   // [k][i], later reused as C-tile [i][j]
    __shared__ float ys[64][65];   // [k][j]
    int b  = blockIdx.z;
    int i0 = blockIdx.y * 64;
    int j0 = blockIdx.x * 64;
    int tid = threadIdx.x;

    const float* xb = x + ((size_t)b * P + i0) * D;
    const float* yb = y + ((size_t)b * P + j0) * D;
    #pragma unroll
    for (int idx = tid; idx < 4096; idx += 256) {
        int p = idx >> 6, d = idx & 63;
        xs[d][p] = xb[(size_t)p * D + d];
        ys[d][p] = yb[(size_t)p * D + d];
    }
    __syncthreads();

    int tx = tid & 15, ty = tid >> 4;
    float acc[4][4];
    #pragma unroll
    for (int r = 0; r < 4; r++)
        #pragma unroll
        for (int c = 0; c < 4; c++) acc[r][c] = 0.0f;

    #pragma unroll 8
    for (int k = 0; k < 64; k++) {
        float rx[4], ry[4];
        #pragma unroll
        for (int r = 0; r < 4; r++) rx[r] = xs[k][ty * 4 + r];
        #pragma unroll
        for (int c = 0; c < 4; c++) ry[c] = ys[k][tx * 4 + c];
        #pragma unroll
        for (int r = 0; r < 4; r++)
            #pragma unroll
            for (int c = 0; c < 4; c++) acc[r][c] = fmaf(rx[r], ry[c], acc[r][c]);
    }

    float xnr[4], ynr[4];
    #pragma unroll
    for (int r = 0; r < 4; r++) xnr[r] = g_xn[b * P + i0 + ty * 4 + r];
    #pragma unroll
    for (int c = 0; c < 4; c++) ynr[c] = g_yn[b * P + j0 + tx * 4 + c];

    float val[4][4];
    #pragma unroll
    for (int r = 0; r < 4; r++)
        #pragma unroll
        for (int c = 0; c < 4; c++)
            val[r][c] = xnr[r] + ynr[c] - 2.0f * acc[r][c];

    // write C (row-major) with float4
    #pragma unroll
    for (int r = 0; r < 4; r++) {
        int row = i0 + ty * 4 + r;
        float4 v4 = make_float4(val[r][0], val[r][1], val[r][2], val[r][3]);
        *reinterpret_cast<float4*>(Cout + ((size_t)b * P + row) * P + j0 + tx * 4) = v4;
    }

    // stage tile into smem and write transposed copy coalesced
    __syncthreads();   // all xs/ys reads complete
    #pragma unroll
    for (int r = 0; r < 4; r++)
        #pragma unroll
        for (int c = 0; c < 4; c++)
            xs[ty * 4 + r][tx * 4 + c] = val[r][c];
    __syncthreads();
    float* CT = (float*)g_ct4;
    #pragma unroll
    for (int idx = tid; idx < 4096; idx += 256) {
        int jj = idx >> 6, ii = idx & 63;
        CT[((size_t)b * P + (j0 + jj)) * P + (i0 + ii)] = xs[ii][jj];
    }
}

// ---------------- row LSE pass (used for both u and v updates) ----------------
// All global scratch pointers resolved INSIDE device code (never pass
// __device__ symbols as kernel args from host!). Warp per row; row held in
// registers; exp2 only in candidate lanes (warp-divergent branch).
template<bool UPASS>
__global__ void __launch_bounds__(256) k_lse_rows(const float4* __restrict__ C4, int par) {
    if (g_done[par]) {
        if (!UPASS && blockIdx.x == 0 && threadIdx.x == 0) g_done[par ^ 1] = 1;
        return;
    }
    const float4* M4  = UPASS ? C4 : (const float4*)g_ct4;
    const float*  wv  = UPASS ? g_v : g_u;
    float*        outv = UPASS ? g_u : g_v;

    __shared__ __align__(16) float4 vw4[512];
    __shared__ float serr[8];
    __shared__ float red[256];
    int tid = threadIdx.x, lane = tid & 31, warp = tid >> 5;
    int r = blockIdx.x * 8 + warp;
    int b = r >> 11;

    const float4* wb4 = reinterpret_cast<const float4*>(wv + b * P);
    for (int j = tid; j < 512; j += 256) {
        float4 t = wb4[j];
        t.x *= INV; t.y *= INV; t.z *= INV; t.w *= INV;
        vw4[j] = t;
    }
    __syncthreads();

    const float4* R = M4 + (size_t)r * 512;
    float hm[2], hs[2];
    #pragma unroll 1
    for (int h = 0; h < 2; h++) {
        int base = h * 256 + lane;
        float4 w[8];
        #pragma unroll
        for (int q = 0; q < 8; q++) {
            float4 c = R[base + q * 32];
            float4 t = vw4[base + q * 32];
            w[q].x = fmaf(c.x, -INV, t.x);
            w[q].y = fmaf(c.y, -INV, t.y);
            w[q].z = fmaf(c.z, -INV, t.z);
            w[q].w = fmaf(c.w, -INV, t.w);
        }
        float4 m4 = w[0];
        #pragma unroll
        for (int q = 1; q < 8; q++) {
            m4.x = fmaxf(m4.x, w[q].x);
            m4.y = fmaxf(m4.y, w[q].y);
            m4.z = fmaxf(m4.z, w[q].z);
            m4.w = fmaxf(m4.w, w[q].w);
        }
        float lm = fmaxf(fmaxf(m4.x, m4.y), fmaxf(m4.z, m4.w));
        float m = lm;
        #pragma unroll
        for (int o = 16; o; o >>= 1) m = fmaxf(m, __shfl_xor_sync(0xffffffffu, m, o));
        float ls = 0.0f;
        if (lm > m - 30.0f) {          // divergent: only candidate lanes issue EX2
            #pragma unroll
            for (int q = 0; q < 8; q++) {
                ls += ex2f(w[q].x - m);
                ls += ex2f(w[q].y - m);
                ls += ex2f(w[q].z - m);
                ls += ex2f(w[q].w - m);
            }
        }
        #pragma unroll
        for (int o = 16; o; o >>= 1) ls += __shfl_xor_sync(0xffffffffu, ls, o);
        hm[h] = m; hs[h] = ls;
    }
    float m = fmaxf(hm[0], hm[1]);
    float s = hs[0] * ex2f(hm[0] - m) + hs[1] * ex2f(hm[1] - m);
    float nv = eps_log_marginal() - EPSLN2 * (m + lg2f_(s));

    if (lane == 0) {
        if (UPASS) {
            float old = outv[r];
            outv[r] = nv;
            serr[warp] = fabsf(nv - old);
        } else {
            outv[r] = nv;
        }
    }

    if (UPASS) {
        __syncthreads();
        if (tid == 0) {
            float e = 0.0f;
            #pragma unroll
            for (int i2 = 0; i2 < 8; i2++) e += serr[i2];
            g_errp[blockIdx.x] = e;
        }
    } else {
        // v-pass block 0 folds the convergence check (g_errp from this
        // iteration's u-pass is complete before this kernel launched).
        if (blockIdx.x == 0) {
            float e = 0.0f;
            for (int t = tid; t < 2048; t += 256) e += g_errp[t];
            red[tid] = e;
            __syncthreads();
            for (int o = 128; o; o >>= 1) {
                if (tid < o) red[tid] += red[tid + o];
                __syncthreads();
            }
            if (tid == 0)
                g_done[par ^ 1] = (red[0] * (1.0f / BATCH) < 0.1f) ? 1 : 0;
        }
    }
}

// ---------------- pi = exp((u+v-C)/eps), partial cost -------------------------
__global__ void __launch_bounds__(256) k_pi(const float4* __restrict__ C4,
                                            float4* __restrict__ pi4) {
    __shared__ __align__(16) float uvw[2048];
    __shared__ float sacc[256];
    int r = blockIdx.x, b = r >> 11, tid = threadIdx.x;
    float ug = g_u[r] * INV;
    for (int j = tid; j < 2048; j += 256) uvw[j] = fmaf(g_v[b * P + j], INV, ug);
    __syncthreads();

    const float4* Crow = C4 + (size_t)r * 512;
    float4* prow = pi4 + (size_t)r * 512;
    const float4* uvw4 = reinterpret_cast<const float4*>(uvw);
    float acc = 0.0f;
    #pragma unroll 2
    for (int j4 = tid; j4 < 512; j4 += 256) {
        float4 c = Crow[j4];
        float4 t = uvw4[j4];
        float4 p;
        p.x = ex2f(fmaf(c.x, -INV, t.x));
        p.y = ex2f(fmaf(c.y, -INV, t.y));
        p.z = ex2f(fmaf(c.z, -INV, t.z));
        p.w = ex2f(fmaf(c.w, -INV, t.w));
        prow[j4] = p;
        acc = fmaf(p.x, c.x, fmaf(p.y, c.y, fmaf(p.z, c.z, fmaf(p.w, c.w, acc))));
    }
    sacc[tid] = acc;
    __syncthreads();
    for (int o = 128; o; o >>= 1) {
        if (tid < o) sacc[tid] += sacc[tid + o];
        __syncthreads();
    }
    if (tid == 0) g_costp[r] = sacc[0];
}

__global__ void k_costred(float* __restrict__ costOut) {
    __shared__ float sb[256];
    int b = blockIdx.x;
    float e = 0.0f;
    for (int t = threadIdx.x; t < P; t += 256) e += g_costp[b * P + t];
    sb[threadIdx.x] = e;
    __syncthreads();
    for (int o = 128; o; o >>= 1) {
        if (threadIdx.x < o) sb[threadIdx.x] += sb[threadIdx.x + o];
        __syncthreads();
    }
    if (threadIdx.x == 0) costOut[b] = sb[0];
}

// ---------------- launch ------------------------------------------------------
extern "C" void kernel_launch(void* const* d_in, const int* in_sizes, int n_in,
                              void* d_out, int out_size) {
    (void)in_sizes; (void)n_in; (void)out_size;
    const float* x = (const float*)d_in[0];
    const float* y = (const float*)d_in[1];
    float* out  = (float*)d_out;
    float* cost = out;                      // [8]
    float* pi   = out + 8;                  // [8,2048,2048]
    float* Cm   = out + 8 + NMAT;           // [8,2048,2048]
    const float4* Cm4 = (const float4*)Cm;

    k_init<<<64, 256>>>();
    k_norm<<<4096, 256>>>(x, y);
    dim3 cg(32, 32, 8);
    k_costmat<<<cg, 256>>>(x, y, Cm);

    for (int k = 0; k < 100; k++) {
        int par = k & 1;
        k_lse_rows<true ><<<2048, 256>>>(Cm4, par);   // u update (rows of C)
        k_lse_rows<false><<<2048, 256>>>(Cm4, par);   // v update (rows of C^T)
    }

    k_pi<<<16384, 256>>>(Cm4, (float4*)pi);
    k_costred<<<8, 256>>>(cost);
}

// round 5
// speedup vs baseline: 1.6374x; 1.3731x over previous
#include <cuda_runtime.h>
#include <cstdint>
#include <cstddef>

#define BATCH 8
#define P 2048
#define D 64
#define FEPS 0.1f
// log2(e)/eps
#define INV 14.426950408889634f
// eps*ln(2)
#define EPSLN2 0.06931471805599453f
#define NMAT ((size_t)BATCH * P * P)

// ---------------- scratch (static device globals; no runtime allocation) ----
__device__ __align__(16) float g_u[BATCH * P];
__device__ __align__(16) float g_v[BATCH * P];
__device__ float g_xn[BATCH * P];
__device__ float g_yn[BATCH * P];
__device__ float g_errp[2048];           // per-U-block |du| partials
__device__ float g_costp[BATCH * P];     // per-row pi*C partials
__device__ int   g_done[2];              // parity double-buffered freeze flag
__device__ __align__(16) float4 g_ct4[NMAT / 4];  // C transposed (134MB scratch)

__device__ __forceinline__ float ex2f(float x) {
    float r; asm("ex2.approx.f32 %0, %1;" : "=f"(r) : "f"(x)); return r;
}
__device__ __forceinline__ float lg2f_(float x) {
    float r; asm("lg2.approx.f32 %0, %1;" : "=f"(r) : "f"(x)); return r;
}
__device__ __forceinline__ float eps_log_marginal() {
    return FEPS * logf(1.0f / 2048.0f + 1e-8f);
}
__device__ __forceinline__ uint32_t smem_u32(const void* p) {
    return (uint32_t)__cvta_generic_to_shared(p);
}
__device__ __forceinline__ void mbar_wait0(uint32_t mbar) {
    asm volatile(
        "{\n\t.reg .pred P;\n\t"
        "W%=: mbarrier.try_wait.parity.acquire.cta.shared::cta.b64 P, [%0], 0;\n\t"
        "@!P bra W%=;\n\t}"
        :: "r"(mbar) : "memory");
}

// ---------------- init --------------------------------------------------------
__global__ void k_init() {
    int i = blockIdx.x * blockDim.x + threadIdx.x;
    if (i < BATCH * P) { g_u[i] = 0.0f; g_v[i] = 0.0f; }
    if (i == 0) { g_done[0] = 0; g_done[1] = 0; }
}

// ---------------- squared norms (warp per point) ------------------------------
__global__ void k_norm(const float* __restrict__ x, const float* __restrict__ y) {
    int gw   = (blockIdx.x * blockDim.x + threadIdx.x) >> 5;
    int lane = threadIdx.x & 31;
    if (gw >= 2 * BATCH * P) return;
    bool isx = gw < BATCH * P;
    int p = isx ? gw : gw - BATCH * P;
    const float* src = isx ? x : y;
    float a0 = src[(size_t)p * D + lane];
    float a1 = src[(size_t)p * D + 32 + lane];
    float s = a0 * a0 + a1 * a1;
    #pragma unroll
    for (int o = 16; o; o >>= 1) s += __shfl_xor_sync(0xffffffffu, s, o);
    if (lane == 0) (isx ? g_xn : g_yn)[p] = s;
}

// ---------------- C = ||x||^2 + ||y||^2 - 2 x.y  (+ transposed copy) ----------
__global__ void k_costmat(const float* __restrict__ x, const float* __restrict__ y,
                          float* __restrict__ Cout) {
    __shared__ float xs[64][65];   // [k][i], later reused as C-tile [i][j]
    __shared__ float ys[64][65];   // [k][j]
    int b  = blockIdx.z;
    int i0 = blockIdx.y * 64;
    int j0 = blockIdx.x * 64;
    int tid = threadIdx.x;

    const float* xb = x + ((size_t)b * P + i0) * D;
    const float* yb = y + ((size_t)b * P + j0) * D;
    #pragma unroll
    for (int idx = tid; idx < 4096; idx += 256) {
        int p = idx >> 6, d = idx & 63;
        xs[d][p] = xb[(size_t)p * D + d];
        ys[d][p] = yb[(size_t)p * D + d];
    }
    __syncthreads();

    int tx = tid & 15, ty = tid >> 4;
    float acc[4][4];
    #pragma unroll
    for (int r = 0; r < 4; r++)
        #pragma unroll
        for (int c = 0; c < 4; c++) acc[r][c] = 0.0f;

    #pragma unroll 8
    for (int k = 0; k < 64; k++) {
        float rx[4], ry[4];
        #pragma unroll
        for (int r = 0; r < 4; r++) rx[r] = xs[k][ty * 4 + r];
        #pragma unroll
        for (int c = 0; c < 4; c++) ry[c] = ys[k][tx * 4 + c];
        #pragma unroll
        for (int r = 0; r < 4; r++)
            #pragma unroll
            for (int c = 0; c < 4; c++) acc[r][c] = fmaf(rx[r], ry[c], acc[r][c]);
    }

    float xnr[4], ynr[4];
    #pragma unroll
    for (int r = 0; r < 4; r++) xnr[r] = g_xn[b * P + i0 + ty * 4 + r];
    #pragma unroll
    for (int c = 0; c < 4; c++) ynr[c] = g_yn[b * P + j0 + tx * 4 + c];

    float val[4][4];
    #pragma unroll
    for (int r = 0; r < 4; r++)
        #pragma unroll
        for (int c = 0; c < 4; c++)
            val[r][c] = xnr[r] + ynr[c] - 2.0f * acc[r][c];

    // write C (row-major) with float4
    #pragma unroll
    for (int r = 0; r < 4; r++) {
        int row = i0 + ty * 4 + r;
        float4 v4 = make_float4(val[r][0], val[r][1], val[r][2], val[r][3]);
        *reinterpret_cast<float4*>(Cout + ((size_t)b * P + row) * P + j0 + tx * 4) = v4;
    }

    // stage tile into smem and write transposed copy coalesced
    __syncthreads();   // all xs/ys reads complete
    #pragma unroll
    for (int r = 0; r < 4; r++)
        #pragma unroll
        for (int c = 0; c < 4; c++)
            xs[ty * 4 + r][tx * 4 + c] = val[r][c];
    __syncthreads();
    float* CT = (float*)g_ct4;
    #pragma unroll
    for (int idx = tid; idx < 4096; idx += 256) {
        int jj = idx >> 6, ii = idx & 63;
        CT[((size_t)b * P + (j0 + jj)) * P + (i0 + ii)] = xs[ii][jj];
    }
}

// ---------------- row LSE pass (used for both u and v updates) ----------------
// Block = 8 contiguous rows (64KB) staged into smem via ONE cp.async.bulk
// against an mbarrier (decouples DRAM streaming from the compute chain).
// Warp per row out of smem; exp2 only in candidate lanes (divergent branch).
template<bool UPASS>
__global__ void __launch_bounds__(256) k_lse_rows(const float* __restrict__ Cg, int par) {
    if (g_done[par]) {
        if (!UPASS && blockIdx.x == 0 && threadIdx.x == 0) g_done[par ^ 1] = 1;
        return;
    }
    const float* M    = UPASS ? Cg : (const float*)g_ct4;
    const float* wv   = UPASS ? g_v : g_u;
    float*       outv = UPASS ? g_u : g_v;

    extern __shared__ __align__(128) float tile[];          // 8*2048 floats = 64KB
    __shared__ __align__(16) float vw[P];                   // 8KB
    __shared__ float serr[8];
    __shared__ float red[256];
    __shared__ __align__(8) unsigned long long mbar;

    int tid = threadIdx.x, lane = tid & 31, warp = tid >> 5;
    int r0 = blockIdx.x * 8;
    int b  = r0 >> 11;

    uint32_t mb = smem_u32(&mbar);
    if (tid == 0)
        asm volatile("mbarrier.init.shared.b64 [%0], 1;" :: "r"(mb) : "memory");
    __syncthreads();
    if (tid == 0) {
        asm volatile("mbarrier.arrive.expect_tx.shared.b64 _, [%0], %1;"
                     :: "r"(mb), "r"(65536u) : "memory");
        asm volatile("cp.async.bulk.shared::cta.global.mbarrier::complete_tx::bytes "
                     "[%0], [%1], %2, [%3];"
                     :: "r"(smem_u32(tile)), "l"(M + (size_t)r0 * P),
                        "r"(65536u), "r"(mb) : "memory");
    }

    // load + prescale the dual vector while the bulk copy is in flight
    const float4* wb4 = reinterpret_cast<const float4*>(wv + b * P);
    float4* vw4 = reinterpret_cast<float4*>(vw);
    for (int j = tid; j < 512; j += 256) {
        float4 t = wb4[j];
        t.x *= INV; t.y *= INV; t.z *= INV; t.w *= INV;
        vw4[j] = t;
    }
    __syncthreads();
    mbar_wait0(mb);

    const float4* R = reinterpret_cast<const float4*>(tile) + warp * 512;

    // pass 1: max of w = v*INV - C*INV over the row
    float4 m4 = make_float4(-3.4e38f, -3.4e38f, -3.4e38f, -3.4e38f);
    #pragma unroll
    for (int q = 0; q < 16; q++) {
        float4 c = R[lane + q * 32];
        float4 t = vw4[lane + q * 32];
        m4.x = fmaxf(m4.x, fmaf(c.x, -INV, t.x));
        m4.y = fmaxf(m4.y, fmaf(c.y, -INV, t.y));
        m4.z = fmaxf(m4.z, fmaf(c.z, -INV, t.z));
        m4.w = fmaxf(m4.w, fmaf(c.w, -INV, t.w));
    }
    float lm = fmaxf(fmaxf(m4.x, m4.y), fmaxf(m4.z, m4.w));
    float m = lm;
    #pragma unroll
    for (int o = 16; o; o >>= 1) m = fmaxf(m, __shfl_xor_sync(0xffffffffu, m, o));

    // pass 2: sum exp2(w - m), only candidate lanes issue EX2 (divergent)
    float ls = 0.0f;
    if (lm > m - 30.0f) {
        #pragma unroll
        for (int q = 0; q < 16; q++) {
            float4 c = R[lane + q * 32];
            float4 t = vw4[lane + q * 32];
            ls += ex2f(fmaf(c.x, -INV, t.x) - m);
            ls += ex2f(fmaf(c.y, -INV, t.y) - m);
            ls += ex2f(fmaf(c.z, -INV, t.z) - m);
            ls += ex2f(fmaf(c.w, -INV, t.w) - m);
        }
    }
    #pragma unroll
    for (int o = 16; o; o >>= 1) ls += __shfl_xor_sync(0xffffffffu, ls, o);

    float nv = eps_log_marginal() - EPSLN2 * (m + lg2f_(ls));
    int r = r0 + warp;

    if (lane == 0) {
        if (UPASS) {
            float old = outv[r];
            outv[r] = nv;
            serr[warp] = fabsf(nv - old);
        } else {
            outv[r] = nv;
        }
    }

    if (UPASS) {
        __syncthreads();
        if (tid == 0) {
            float e = 0.0f;
            #pragma unroll
            for (int i2 = 0; i2 < 8; i2++) e += serr[i2];
            g_errp[blockIdx.x] = e;
        }
    } else {
        // v-pass block 0 folds the convergence check (g_errp from this
        // iteration's u-pass is complete before this kernel launched).
        if (blockIdx.x == 0) {
            float e = 0.0f;
            for (int t = tid; t < 2048; t += 256) e += g_errp[t];
            red[tid] = e;
            __syncthreads();
            for (int o = 128; o; o >>= 1) {
                if (tid < o) red[tid] += red[tid + o];
                __syncthreads();
            }
            if (tid == 0)
                g_done[par ^ 1] = (red[0] * (1.0f / BATCH) < 0.1f) ? 1 : 0;
        }
    }
}

// ---------------- pi = exp((u+v-C)/eps), partial cost -------------------------
__global__ void __launch_bounds__(256) k_pi(const float4* __restrict__ C4,
                                            float4* __restrict__ pi4) {
    __shared__ __align__(16) float uvw[2048];
    __shared__ float sacc[256];
    int r = blockIdx.x, b = r >> 11, tid = threadIdx.x;
    float ug = g_u[r] * INV;
    for (int j = tid; j < 2048; j += 256) uvw[j] = fmaf(g_v[b * P + j], INV, ug);
    __syncthreads();

    const float4* Crow = C4 + (size_t)r * 512;
    float4* prow = pi4 + (size_t)r * 512;
    const float4* uvw4 = reinterpret_cast<const float4*>(uvw);
    float acc = 0.0f;
    #pragma unroll 2
    for (int j4 = tid; j4 < 512; j4 += 256) {
        float4 c = Crow[j4];
        float4 t = uvw4[j4];
        float4 p;
        p.x = ex2f(fmaf(c.x, -INV, t.x));
        p.y = ex2f(fmaf(c.y, -INV, t.y));
        p.z = ex2f(fmaf(c.z, -INV, t.z));
        p.w = ex2f(fmaf(c.w, -INV, t.w));
        prow[j4] = p;
        acc = fmaf(p.x, c.x, fmaf(p.y, c.y, fmaf(p.z, c.z, fmaf(p.w, c.w, acc))));
    }
    sacc[tid] = acc;
    __syncthreads();
    for (int o = 128; o; o >>= 1) {
        if (tid < o) sacc[tid] += sacc[tid + o];
        __syncthreads();
    }
    if (tid == 0) g_costp[r] = sacc[0];
}

__global__ void k_costred(float* __restrict__ costOut) {
    __shared__ float sb[256];
    int b = blockIdx.x;
    float e = 0.0f;
    for (int t = threadIdx.x; t < P; t += 256) e += g_costp[b * P + t];
    sb[threadIdx.x] = e;
    __syncthreads();
    for (int o = 128; o; o >>= 1) {
        if (threadIdx.x < o) sb[threadIdx.x] += sb[threadIdx.x + o];
        __syncthreads();
    }
    if (threadIdx.x == 0) costOut[b] = sb[0];
}

// ---------------- launch ------------------------------------------------------
extern "C" void kernel_launch(void* const* d_in, const int* in_sizes, int n_in,
                              void* d_out, int out_size) {
    (void)in_sizes; (void)n_in; (void)out_size;
    const float* x = (const float*)d_in[0];
    const float* y = (const float*)d_in[1];
    float* out  = (float*)d_out;
    float* cost = out;                      // [8]
    float* pi   = out + 8;                  // [8,2048,2048]
    float* Cm   = out + 8 + NMAT;           // [8,2048,2048]

    // opt-in to 64KB dynamic smem (host-side state mutation, not an allocation)
    cudaFuncSetAttribute(k_lse_rows<true>,
                         cudaFuncAttributeMaxDynamicSharedMemorySize, 65536);
    cudaFuncSetAttribute(k_lse_rows<false>,
                         cudaFuncAttributeMaxDynamicSharedMemorySize, 65536);

    k_init<<<64, 256>>>();
    k_norm<<<4096, 256>>>(x, y);
    dim3 cg(32, 32, 8);
    k_costmat<<<cg, 256>>>(x, y, Cm);

    for (int k = 0; k < 100; k++) {
        int par = k & 1;
        k_lse_rows<true ><<<2048, 256, 65536>>>(Cm, par);   // u update (rows of C)
        k_lse_rows<false><<<2048, 256, 65536>>>(Cm, par);   // v update (rows of C^T)
    }

    k_pi<<<16384, 256>>>((const float4*)Cm, (float4*)pi);
    k_costred<<<8, 256>>>(cost);
}

// round 6
// speedup vs baseline: 1.9049x; 1.1634x over previous
#include <cuda_runtime.h>
#include <cstdint>
#include <cstddef>

#define BATCH 8
#define P 2048
#define D 64
#define FEPS 0.1f
// log2(e)/eps
#define INV 14.426950408889634f
// eps*ln(2)
#define EPSLN2 0.06931471805599453f
#define NMAT ((size_t)BATCH * P * P)
#define NTILES 2048          // 8-row tiles per pass
#define NBLK 148             // persistent blocks (1 per SM)
#define TILE_BYTES 65536u    // 8 rows * 2048 * 4B

// ---------------- scratch (static device globals; no runtime allocation) ----
__device__ __align__(16) float g_u[BATCH * P];
__device__ __align__(16) float g_v[BATCH * P];
__device__ float g_xn[BATCH * P];
__device__ float g_yn[BATCH * P];
__device__ float g_errp[NTILES];         // per-tile |du| partials
__device__ float g_costp[BATCH * P];     // per-row pi*C partials
__device__ int   g_done[2];              // parity double-buffered freeze flag
__device__ __align__(16) float4 g_ct4[NMAT / 4];  // C transposed (134MB scratch)

__device__ __forceinline__ float ex2f(float x) {
    float r; asm("ex2.approx.f32 %0, %1;" : "=f"(r) : "f"(x)); return r;
}
__device__ __forceinline__ float lg2f_(float x) {
    float r; asm("lg2.approx.f32 %0, %1;" : "=f"(r) : "f"(x)); return r;
}
__device__ __forceinline__ float eps_log_marginal() {
    return FEPS * logf(1.0f / 2048.0f + 1e-8f);
}
__device__ __forceinline__ uint32_t smem_u32(const void* p) {
    return (uint32_t)__cvta_generic_to_shared(p);
}
__device__ __forceinline__ void mbar_wait(uint32_t mbar, uint32_t phase) {
    asm volatile(
        "{\n\t.reg .pred P;\n\t"
        "W%=: mbarrier.try_wait.parity.acquire.cta.shared::cta.b64 P, [%0], %1;\n\t"
        "@!P bra W%=;\n\t}"
        :: "r"(mbar), "r"(phase) : "memory");
}
__device__ __forceinline__ void issue_copy(uint32_t smem_dst, const float* src, uint32_t mbar) {
    asm volatile("mbarrier.arrive.expect_tx.shared.b64 _, [%0], %1;"
                 :: "r"(mbar), "r"(TILE_BYTES) : "memory");
    asm volatile("cp.async.bulk.shared::cta.global.mbarrier::complete_tx::bytes "
                 "[%0], [%1], %2, [%3];"
                 :: "r"(smem_dst), "l"(src), "r"(TILE_BYTES), "r"(mbar) : "memory");
}

// ---------------- init --------------------------------------------------------
__global__ void k_init() {
    int i = blockIdx.x * blockDim.x + threadIdx.x;
    if (i < BATCH * P) { g_u[i] = 0.0f; g_v[i] = 0.0f; }
    if (i == 0) { g_done[0] = 0; g_done[1] = 0; }
}

// ---------------- squared norms (warp per point) ------------------------------
__global__ void k_norm(const float* __restrict__ x, const float* __restrict__ y) {
    int gw   = (blockIdx.x * blockDim.x + threadIdx.x) >> 5;
    int lane = threadIdx.x & 31;
    if (gw >= 2 * BATCH * P) return;
    bool isx = gw < BATCH * P;
    int p = isx ? gw : gw - BATCH * P;
    const float* src = isx ? x : y;
    float a0 = src[(size_t)p * D + lane];
    float a1 = src[(size_t)p * D + 32 + lane];
    float s = a0 * a0 + a1 * a1;
    #pragma unroll
    for (int o = 16; o; o >>= 1) s += __shfl_xor_sync(0xffffffffu, s, o);
    if (lane == 0) (isx ? g_xn : g_yn)[p] = s;
}

// ---------------- C = ||x||^2 + ||y||^2 - 2 x.y  (+ transposed copy) ----------
__global__ void k_costmat(const float* __restrict__ x, const float* __restrict__ y,
                          float* __restrict__ Cout) {
    __shared__ float xs[64][65];   // [k][i], later reused as C-tile [i][j]
    __shared__ float ys[64][65];   // [k][j]
    int b  = blockIdx.z;
    int i0 = blockIdx.y * 64;
    int j0 = blockIdx.x * 64;
    int tid = threadIdx.x;

    const float* xb = x + ((size_t)b * P + i0) * D;
    const float* yb = y + ((size_t)b * P + j0) * D;
    #pragma unroll
    for (int idx = tid; idx < 4096; idx += 256) {
        int p = idx >> 6, d = idx & 63;
        xs[d][p] = xb[(size_t)p * D + d];
        ys[d][p] = yb[(size_t)p * D + d];
    }
    __syncthreads();

    int tx = tid & 15, ty = tid >> 4;
    float acc[4][4];
    #pragma unroll
    for (int r = 0; r < 4; r++)
        #pragma unroll
        for (int c = 0; c < 4; c++) acc[r][c] = 0.0f;

    #pragma unroll 8
    for (int k = 0; k < 64; k++) {
        float rx[4], ry[4];
        #pragma unroll
        for (int r = 0; r < 4; r++) rx[r] = xs[k][ty * 4 + r];
        #pragma unroll
        for (int c = 0; c < 4; c++) ry[c] = ys[k][tx * 4 + c];
        #pragma unroll
        for (int r = 0; r < 4; r++)
            #pragma unroll
            for (int c = 0; c < 4; c++) acc[r][c] = fmaf(rx[r], ry[c], acc[r][c]);
    }

    float xnr[4], ynr[4];
    #pragma unroll
    for (int r = 0; r < 4; r++) xnr[r] = g_xn[b * P + i0 + ty * 4 + r];
    #pragma unroll
    for (int c = 0; c < 4; c++) ynr[c] = g_yn[b * P + j0 + tx * 4 + c];

    float val[4][4];
    #pragma unroll
    for (int r = 0; r < 4; r++)
        #pragma unroll
        for (int c = 0; c < 4; c++)
            val[r][c] = xnr[r] + ynr[c] - 2.0f * acc[r][c];

    #pragma unroll
    for (int r = 0; r < 4; r++) {
        int row = i0 + ty * 4 + r;
        float4 v4 = make_float4(val[r][0], val[r][1], val[r][2], val[r][3]);
        *reinterpret_cast<float4*>(Cout + ((size_t)b * P + row) * P + j0 + tx * 4) = v4;
    }

    // stage tile into smem and write transposed copy coalesced
    __syncthreads();
    #pragma unroll
    for (int r = 0; r < 4; r++)
        #pragma unroll
        for (int c = 0; c < 4; c++)
            xs[ty * 4 + r][tx * 4 + c] = val[r][c];
    __syncthreads();
    float* CT = (float*)g_ct4;
    #pragma unroll
    for (int idx = tid; idx < 4096; idx += 256) {
        int jj = idx >> 6, ii = idx & 63;
        CT[((size_t)b * P + (j0 + jj)) * P + (i0 + ii)] = xs[ii][jj];
    }
}

// ---------------- persistent pipelined row-LSE pass ---------------------------
// 148 blocks, 1/SM, 3-stage 64KB smem pipeline over contiguous 8-row tiles.
template<bool UPASS>
__global__ void __launch_bounds__(256, 1) k_lse_pipe(const float* __restrict__ Cg, int par) {
    if (g_done[par]) {
        if (!UPASS && blockIdx.x == 0 && threadIdx.x == 0) g_done[par ^ 1] = 1;
        return;
    }
    const float* M    = UPASS ? Cg : (const float*)g_ct4;
    const float* wv   = UPASS ? g_v : g_u;
    float*       outv = UPASS ? g_u : g_v;

    extern __shared__ __align__(128) float tile[];      // 3 * 16384 floats
    __shared__ __align__(16) float vw[P];
    __shared__ float serr[8];
    __shared__ float red[256];
    __shared__ __align__(8) unsigned long long mbars[3];

    int tid = threadIdx.x, lane = tid & 31, warp = tid >> 5;
    int t0 = (int)(((long long)blockIdx.x * NTILES) / NBLK);
    int t1 = (int)(((long long)(blockIdx.x + 1) * NTILES) / NBLK);

    uint32_t mb0 = smem_u32(&mbars[0]);
    if (tid == 0) {
        #pragma unroll
        for (int s = 0; s < 3; s++)
            asm volatile("mbarrier.init.shared.b64 [%0], 1;" :: "r"(mb0 + 8 * s) : "memory");
    }
    __syncthreads();

    if (tid == 0) {
        #pragma unroll
        for (int s = 0; s < 3; s++)
            if (t0 + s < t1)
                issue_copy(smem_u32(tile + s * 16384), M + (size_t)(t0 + s) * (8 * P), mb0 + 8 * s);
    }

    // v-pass: fold convergence check for next iteration (g_errp complete
    // from the u-kernel that already finished).
    if (!UPASS && blockIdx.x == 0) {
        float e = 0.0f;
        for (int t = tid; t < NTILES; t += 256) e += g_errp[t];
        red[tid] = e;
        __syncthreads();
        for (int o = 128; o; o >>= 1) {
            if (tid < o) red[tid] += red[tid + o];
            __syncthreads();
        }
        if (tid == 0)
            g_done[par ^ 1] = (red[0] * (1.0f / BATCH) < 0.1f) ? 1 : 0;
    }

    const float4* vw4 = reinterpret_cast<const float4*>(vw);
    int cur_b = -1;
    int phase[3] = {0, 0, 0};

    for (int k = t0; k < t1; k++) {
        int b = k >> 8;                          // 256 tiles per batch
        if (b != cur_b) {
            __syncthreads();
            const float4* wb4 = reinterpret_cast<const float4*>(wv + b * P);
            float4* vwd = reinterpret_cast<float4*>(vw);
            for (int j = tid; j < 512; j += 256) {
                float4 t = wb4[j];
                t.x *= INV; t.y *= INV; t.z *= INV; t.w *= INV;
                vwd[j] = t;
            }
            __syncthreads();
            cur_b = b;
        }

        int s = (k - t0) % 3;
        mbar_wait(mb0 + 8 * s, (uint32_t)phase[s]);
        phase[s] ^= 1;

        const float4* R = reinterpret_cast<const float4*>(tile + s * 16384) + warp * 512;

        // pass 1: max of w = v*INV - C*INV over the row
        float4 m4 = make_float4(-3.4e38f, -3.4e38f, -3.4e38f, -3.4e38f);
        #pragma unroll
        for (int q = 0; q < 16; q++) {
            float4 c = R[lane + q * 32];
            float4 t = vw4[lane + q * 32];
            m4.x = fmaxf(m4.x, fmaf(c.x, -INV, t.x));
            m4.y = fmaxf(m4.y, fmaf(c.y, -INV, t.y));
            m4.z = fmaxf(m4.z, fmaf(c.z, -INV, t.z));
            m4.w = fmaxf(m4.w, fmaf(c.w, -INV, t.w));
        }
        float lm = fmaxf(fmaxf(m4.x, m4.y), fmaxf(m4.z, m4.w));
        float m = lm;
        #pragma unroll
        for (int o = 16; o; o >>= 1) m = fmaxf(m, __shfl_xor_sync(0xffffffffu, m, o));

        // pass 2: only candidate lanes issue EX2 (divergent branch)
        float ls = 0.0f;
        if (lm > m - 30.0f) {
            #pragma unroll
            for (int q = 0; q < 16; q++) {
                float4 c = R[lane + q * 32];
                float4 t = vw4[lane + q * 32];
                ls += ex2f(fmaf(c.x, -INV, t.x) - m);
                ls += ex2f(fmaf(c.y, -INV, t.y) - m);
                ls += ex2f(fmaf(c.z, -INV, t.z) - m);
                ls += ex2f(fmaf(c.w, -INV, t.w) - m);
            }
        }
        #pragma unroll
        for (int o = 16; o; o >>= 1) ls += __shfl_xor_sync(0xffffffffu, ls, o);

        float nv = eps_log_marginal() - EPSLN2 * (m + lg2f_(ls));
        int r = k * 8 + warp;
        if (lane == 0) {
            if (UPASS) {
                float old = outv[r];
                outv[r] = nv;
                serr[warp] = fabsf(nv - old);
            } else {
                outv[r] = nv;
            }
        }
        __syncthreads();   // all reads of stage s + serr writes complete
        if (UPASS && tid == 0) {
            float e = 0.0f;
            #pragma unroll
            for (int i2 = 0; i2 < 8; i2++) e += serr[i2];
            g_errp[k] = e;
        }
        if (tid == 0 && k + 3 < t1)
            issue_copy(smem_u32(tile + s * 16384), M + (size_t)(k + 3) * (8 * P), mb0 + 8 * s);
    }
}

// ---------------- pi = exp((u+v-C)/eps), partial cost -------------------------
__global__ void __launch_bounds__(256) k_pi(const float4* __restrict__ C4,
                                            float4* __restrict__ pi4) {
    __shared__ __align__(16) float uvw[2048];
    __shared__ float sacc[256];
    int r = blockIdx.x, b = r >> 11, tid = threadIdx.x;
    float ug = g_u[r] * INV;
    for (int j = tid; j < 2048; j += 256) uvw[j] = fmaf(g_v[b * P + j], INV, ug);
    __syncthreads();

    const float4* Crow = C4 + (size_t)r * 512;
    float4* prow = pi4 + (size_t)r * 512;
    const float4* uvw4 = reinterpret_cast<const float4*>(uvw);
    float acc = 0.0f;
    #pragma unroll 2
    for (int j4 = tid; j4 < 512; j4 += 256) {
        float4 c = Crow[j4];
        float4 t = uvw4[j4];
        float4 p;
        p.x = ex2f(fmaf(c.x, -INV, t.x));
        p.y = ex2f(fmaf(c.y, -INV, t.y));
        p.z = ex2f(fmaf(c.z, -INV, t.z));
        p.w = ex2f(fmaf(c.w, -INV, t.w));
        prow[j4] = p;
        acc = fmaf(p.x, c.x, fmaf(p.y, c.y, fmaf(p.z, c.z, fmaf(p.w, c.w, acc))));
    }
    sacc[tid] = acc;
    __syncthreads();
    for (int o = 128; o; o >>= 1) {
        if (tid < o) sacc[tid] += sacc[tid + o];
        __syncthreads();
    }
    if (tid == 0) g_costp[r] = sacc[0];
}

__global__ void k_costred(float* __restrict__ costOut) {
    __shared__ float sb[256];
    int b = blockIdx.x;
    float e = 0.0f;
    for (int t = threadIdx.x; t < P; t += 256) e += g_costp[b * P + t];
    sb[threadIdx.x] = e;
    __syncthreads();
    for (int o = 128; o; o >>= 1) {
        if (threadIdx.x < o) sb[threadIdx.x] += sb[threadIdx.x + o];
        __syncthreads();
    }
    if (threadIdx.x == 0) costOut[b] = sb[0];
}

// ---------------- launch ------------------------------------------------------
extern "C" void kernel_launch(void* const* d_in, const int* in_sizes, int n_in,
                              void* d_out, int out_size) {
    (void)in_sizes; (void)n_in; (void)out_size;
    const float* x = (const float*)d_in[0];
    const float* y = (const float*)d_in[1];
    float* out  = (float*)d_out;
    float* cost = out;                      // [8]
    float* pi   = out + 8;                  // [8,2048,2048]
    float* Cm   = out + 8 + NMAT;           // [8,2048,2048]

    // opt-in to 192KB dynamic smem (host-side attribute, not an allocation)
    cudaFuncSetAttribute(k_lse_pipe<true>,
                         cudaFuncAttributeMaxDynamicSharedMemorySize, 3 * 65536);
    cudaFuncSetAttribute(k_lse_pipe<false>,
                         cudaFuncAttributeMaxDynamicSharedMemorySize, 3 * 65536);

    k_init<<<64, 256>>>();
    k_norm<<<4096, 256>>>(x, y);
    dim3 cg(32, 32, 8);
    k_costmat<<<cg, 256>>>(x, y, Cm);

    for (int k = 0; k < 100; k++) {
        int par = k & 1;
        k_lse_pipe<true ><<<NBLK, 256, 3 * 65536>>>(Cm, par);   // u update (rows of C)
        k_lse_pipe<false><<<NBLK, 256, 3 * 65536>>>(Cm, par);   // v update (rows of C^T)
    }

    k_pi<<<16384, 256>>>((const float4*)Cm, (float4*)pi);
    k_costred<<<8, 256>>>(cost);
}